// round 4
// baseline (speedup 1.0000x reference)
#include <cuda_runtime.h>
#include <math.h>

#define NN 50000
#define EE 800000
#define HH 128
#define NHH 8
#define DD 16
#define TT 6
#define LL 2

// ---------------- scratch (device globals; no allocation allowed) ----------------
__device__ float g_h[NN * HH];       // pos-injected h (per layer)
__device__ float g_kt[NN * HH];      // (h @ WkA[t])  -- rel_att/pri/scale folded in
__device__ float g_q[NN * HH];       // (h @ Wq[t])
__device__ float g_vm[NN * HH];      // (h @ WvM[t])  -- rel_msg folded in
__device__ float g_trans[NN * HH];   // gelu(agg)
__device__ float g_hid[NN * HH];     // hidden state between layers
__device__ float g_cn[NN * HH];      // cn state between layers
__device__ float g_hgt[NN * HH];     // hgt_out (for priority)
__device__ float g_wka[TT * HH * HH];
__device__ float g_wvm[TT * HH * HH];
__device__ int g_tcnt[TT];
__device__ int g_toff[TT + 1];
__device__ int g_tcur[TT];
__device__ int g_tnodes[NN];
__device__ int g_dcnt[NN];
__device__ int g_doff[NN + 1];
__device__ int g_dcur[NN];
__device__ int g_csrc[EE];

// ---------------- helpers ----------------
__device__ __forceinline__ float geluf(float x) {
    float x3 = x * x * x;
    return 0.5f * x * (1.0f + tanhf(0.7978845608028654f * (x + 0.044715f * x3)));
}

// ---------------- setup kernels ----------------
__global__ void k_zero() {
    int i = blockIdx.x * blockDim.x + threadIdx.x;
    int stride = gridDim.x * blockDim.x;
    for (int j = i; j < NN; j += stride) { g_dcnt[j] = 0; g_dcur[j] = 0; }
    if (i < TT) { g_tcnt[i] = 0; g_tcur[i] = 0; }
}

__global__ void k_count(const int* __restrict__ edst, const int* __restrict__ nt) {
    __shared__ int sh[TT];
    int tid = threadIdx.x;
    if (tid < TT) sh[tid] = 0;
    __syncthreads();
    int i = blockIdx.x * blockDim.x + tid;
    int stride = gridDim.x * blockDim.x;
    for (int e = i; e < EE; e += stride) atomicAdd(&g_dcnt[edst[e]], 1);
    for (int n = i; n < NN; n += stride) atomicAdd(&sh[nt[n]], 1);
    __syncthreads();
    if (tid < TT) atomicAdd(&g_tcnt[tid], sh[tid]);
}

__global__ void k_toff() {
    if (threadIdx.x == 0 && blockIdx.x == 0) {
        int r = 0;
        for (int t = 0; t < TT; t++) { g_toff[t] = r; r += g_tcnt[t]; }
        g_toff[TT] = r;
    }
}

// single-block exclusive scan of g_dcnt -> g_doff
__global__ void k_scan() {
    __shared__ int wsum[32];
    __shared__ int carry;
    int tid = threadIdx.x, lane = tid & 31, wid = tid >> 5;
    if (tid == 0) carry = 0;
    __syncthreads();
    for (int start = 0; start < NN; start += 1024) {
        int i = start + tid;
        int v = (i < NN) ? g_dcnt[i] : 0;
        int x = v;
        #pragma unroll
        for (int o = 1; o < 32; o <<= 1) {
            int y = __shfl_up_sync(0xffffffffu, x, o);
            if (lane >= o) x += y;
        }
        if (lane == 31) wsum[wid] = x;
        __syncthreads();
        if (wid == 0) {
            int w = wsum[lane];
            #pragma unroll
            for (int o = 1; o < 32; o <<= 1) {
                int y = __shfl_up_sync(0xffffffffu, w, o);
                if (lane >= o) w += y;
            }
            wsum[lane] = w;
        }
        __syncthreads();
        int incl = x + (wid > 0 ? wsum[wid - 1] : 0);
        int excl = carry + incl - v;
        if (i < NN) g_doff[i] = excl;
        int btot = wsum[31];
        __syncthreads();
        if (tid == 0) carry += btot;
        __syncthreads();
    }
    if (tid == 0) g_doff[NN] = carry;
}

__global__ void k_scatter(const int* __restrict__ nt, const int* __restrict__ esrc,
                          const int* __restrict__ edst) {
    int i = blockIdx.x * blockDim.x + threadIdx.x;
    int stride = gridDim.x * blockDim.x;
    for (int n = i; n < NN; n += stride) {
        int t = nt[n];
        int p = atomicAdd(&g_tcur[t], 1);
        g_tnodes[g_toff[t] + p] = n;
    }
    for (int e = i; e < EE; e += stride) {
        int d = edst[e];
        int p = atomicAdd(&g_dcur[d], 1);
        g_csrc[g_doff[d] + p] = esrc[e];
    }
}

// ---------------- per-layer kernels ----------------
// Fold rel_att (with rel_pri * D^-1/2) into Wk, rel_msg into Wv.
__global__ void k_combine(const float* __restrict__ Wk, const float* __restrict__ Wv,
                          const float* __restrict__ rel_att, const float* __restrict__ rel_msg,
                          const float* __restrict__ rel_pri, int l) {
    int t = blockIdx.x, mat = blockIdx.y;
    __shared__ float sA[NHH * DD * DD];
    __shared__ float sScl[NHH];
    const float* W = (mat == 0 ? Wk : Wv) + (size_t)(l * TT + t) * HH * HH;
    const float* A = (mat == 0 ? rel_att : rel_msg) + (size_t)l * NHH * DD * DD;
    float* out = (mat == 0 ? g_wka : g_wvm) + (size_t)t * HH * HH;
    for (int idx = threadIdx.x; idx < NHH * DD * DD; idx += blockDim.x) sA[idx] = A[idx];
    if (threadIdx.x < NHH)
        sScl[threadIdx.x] = (mat == 0) ? rel_pri[l * NHH + threadIdx.x] * 0.25f : 1.0f;
    __syncthreads();
    for (int idx = threadIdx.x; idx < HH * HH; idx += blockDim.x) {
        int i = idx >> 7, c = idx & 127, h = c >> 4, f = c & 15;
        float s = 0.0f;
        #pragma unroll
        for (int d = 0; d < DD; d++)
            s += W[i * HH + h * DD + d] * sA[h * DD * DD + d * DD + f];
        out[idx] = s * sScl[h];
    }
}

// h = hidden + x_norm_abs @ W_pos[l]
__global__ void k_pos(const float* __restrict__ ext_hidden, const float* __restrict__ xn,
                      const float* __restrict__ Wpos, int l) {
    int i = blockIdx.x * blockDim.x + threadIdx.x;
    if (i >= NN * HH) return;
    const float* hin = (l == 0) ? ext_hidden : g_hid;
    int n = i >> 7, j = i & 127;
    const float* wp = Wpos + l * 2 * HH;
    g_h[i] = hin[i] + xn[2 * n] * wp[j] + xn[2 * n + 1] * wp[HH + j];
}

// grouped-by-type GEMM: kt/q/vm = h @ {WkA, Wq, WvM}[t]. 32-node tile, 128 threads,
// 3 matrices fused so each shared h-load feeds 3 FFMAs.
__global__ void __launch_bounds__(128) k_proj(const float* __restrict__ Wq, int l) {
    int t = blockIdx.y;
    int beg = g_toff[t], end = g_toff[t + 1];
    int base = beg + (int)blockIdx.x * 32;
    if (base >= end) return;
    int cnt = min(32, end - base);
    __shared__ float hs[32][HH];
    __shared__ int nidx[32];
    int tid = threadIdx.x;
    if (tid < 32) nidx[tid] = (tid < cnt) ? g_tnodes[base + tid] : 0;
    __syncthreads();
    #pragma unroll 4
    for (int i = 0; i < 32; i++)
        hs[i][tid] = (i < cnt) ? g_h[(size_t)nidx[i] * HH + tid] : 0.0f;
    __syncthreads();
    const float* wk = g_wka + (size_t)t * HH * HH;
    const float* wq = Wq + (size_t)(l * TT + t) * HH * HH;
    const float* wv = g_wvm + (size_t)t * HH * HH;
    float ak[32], aq[32], av[32];
    #pragma unroll
    for (int i = 0; i < 32; i++) { ak[i] = 0.f; aq[i] = 0.f; av[i] = 0.f; }
    for (int h = 0; h < HH; h++) {
        float wkv = wk[h * HH + tid];
        float wqv = wq[h * HH + tid];
        float wvv = wv[h * HH + tid];
        #pragma unroll
        for (int i = 0; i < 32; i++) {
            float hv = hs[i][h];
            ak[i] += hv * wkv;
            aq[i] += hv * wqv;
            av[i] += hv * wvv;
        }
    }
    for (int i = 0; i < cnt; i++) {
        size_t off = (size_t)nidx[i] * HH + tid;
        g_kt[off] = ak[i];
        g_q[off] = aq[i];
        g_vm[off] = av[i];
    }
}

// one warp per destination node: online softmax over incoming edges + message agg + gelu
__global__ void k_edge() {
    int warp = threadIdx.x >> 5, lane = threadIdx.x & 31;
    int n = blockIdx.x * 8 + warp;
    if (n >= NN) return;
    int beg = g_doff[n], end = g_doff[n + 1];
    float4 q4 = *(const float4*)(g_q + (size_t)n * HH + lane * 4);
    float m = -1e30f, den = 0.0f;
    float ax = 0.f, ay = 0.f, az = 0.f, aw = 0.f;
    for (int b = beg; b < end; b += 32) {
        int nchunk = min(32, end - b);
        int srcs = (b + lane < end) ? g_csrc[b + lane] : 0;
        for (int j = 0; j < nchunk; j++) {
            int src = __shfl_sync(0xffffffffu, srcs, j);
            float4 kt4 = *(const float4*)(g_kt + (size_t)src * HH + lane * 4);
            float s = kt4.x * q4.x + kt4.y * q4.y + kt4.z * q4.z + kt4.w * q4.w;
            s += __shfl_xor_sync(0xffffffffu, s, 1);
            s += __shfl_xor_sync(0xffffffffu, s, 2);   // per-head att (head = lane/4)
            float nm = fmaxf(m, s);
            float sc = __expf(m - nm);
            float p = __expf(s - nm);
            float4 vm4 = *(const float4*)(g_vm + (size_t)src * HH + lane * 4);
            den = den * sc + p;
            ax = ax * sc + p * vm4.x;
            ay = ay * sc + p * vm4.y;
            az = az * sc + p * vm4.z;
            aw = aw * sc + p * vm4.w;
            m = nm;
        }
    }
    float inv = 1.0f / (den + 1e-16f);
    float4 o;
    o.x = geluf(ax * inv);
    o.y = geluf(ay * inv);
    o.z = geluf(az * inv);
    o.w = geluf(aw * inv);
    *(float4*)(g_trans + (size_t)n * HH + lane * 4) = o;
}

// out = trans @ Wa[t], fused epilogue: skip mix, cn/hidden updates, store hgt
__global__ void __launch_bounds__(128) k_out(const float* __restrict__ Wa,
                                             const float* __restrict__ skip,
                                             const float* __restrict__ ext_cn,
                                             const float* __restrict__ ext_hidden,
                                             float* __restrict__ out_cn,
                                             float* __restrict__ out_hid, int l) {
    int t = blockIdx.y;
    int beg = g_toff[t], end = g_toff[t + 1];
    int base = beg + (int)blockIdx.x * 32;
    if (base >= end) return;
    int cnt = min(32, end - base);
    __shared__ float ts[32][HH];
    __shared__ int nidx[32];
    __shared__ float ssk;
    int tid = threadIdx.x;
    if (tid < 32) nidx[tid] = (tid < cnt) ? g_tnodes[base + tid] : 0;
    if (tid == 0) ssk = 1.0f / (1.0f + __expf(-skip[l * TT + t]));
    __syncthreads();
    #pragma unroll 4
    for (int i = 0; i < 32; i++)
        ts[i][tid] = (i < cnt) ? g_trans[(size_t)nidx[i] * HH + tid] : 0.0f;
    __syncthreads();
    const float* w = Wa + (size_t)(l * TT + t) * HH * HH;
    float acc[32];
    #pragma unroll
    for (int i = 0; i < 32; i++) acc[i] = 0.f;
    for (int h = 0; h < HH; h++) {
        float wv = w[h * HH + tid];
        #pragma unroll
        for (int i = 0; i < 32; i++) acc[i] += ts[i][h] * wv;
    }
    const float* cn_in = (l == 0) ? ext_cn : g_cn;
    const float* hid_in = (l == 0) ? ext_hidden : g_hid;
    float* cn_o = (l == LL - 1) ? out_cn : g_cn;
    float* hid_o = (l == LL - 1) ? out_hid : g_hid;
    float sk = ssk;
    for (int i = 0; i < cnt; i++) {
        size_t off = (size_t)nidx[i] * HH + tid;
        float hgt = sk * acc[i] + (1.0f - sk) * g_h[off];
        g_hgt[off] = hgt;
        float cnew = hgt + cn_in[off];
        float hnew = hid_in[off] + tanhf(cnew);
        cn_o[off] = cnew;
        hid_o[off] = hnew;
    }
}

// priority = sigmoid(hgt @ w_pri[L-1]); warp per node
__global__ void k_pri(const float* __restrict__ w_pri, float* __restrict__ out) {
    int warp = threadIdx.x >> 5, lane = threadIdx.x & 31;
    int n = blockIdx.x * 8 + warp;
    if (n >= NN) return;
    float4 hv = *(const float4*)(g_hgt + (size_t)n * HH + lane * 4);
    float4 wp = *(const float4*)(w_pri + (LL - 1) * HH + lane * 4);
    float s = hv.x * wp.x + hv.y * wp.y + hv.z * wp.z + hv.w * wp.w;
    #pragma unroll
    for (int o = 16; o > 0; o >>= 1) s += __shfl_xor_sync(0xffffffffu, s, o);
    if (lane == 0) out[n] = 1.0f / (1.0f + __expf(-s));
}

// ---------------- launch ----------------
extern "C" void kernel_launch(void* const* d_in, const int* in_sizes, int n_in,
                              void* d_out, int out_size) {
    const float* in_hidden = (const float*)d_in[0];
    const float* in_cn     = (const float*)d_in[1];
    const float* in_x      = (const float*)d_in[2];
    const int*   node_type = (const int*)d_in[3];
    const int*   edge_src  = (const int*)d_in[4];
    const int*   edge_dst  = (const int*)d_in[5];
    const float* W_pos     = (const float*)d_in[6];
    const float* Wk        = (const float*)d_in[7];
    const float* Wq        = (const float*)d_in[8];
    const float* Wv        = (const float*)d_in[9];
    const float* Wa        = (const float*)d_in[10];
    const float* rel_att   = (const float*)d_in[11];
    const float* rel_msg   = (const float*)d_in[12];
    const float* rel_pri   = (const float*)d_in[13];
    const float* skip      = (const float*)d_in[14];
    const float* w_pri     = (const float*)d_in[15];

    float* out = (float*)d_out;
    float* out_hid = out;
    float* out_cn = out + (size_t)NN * HH;
    float* out_pri = out + (size_t)2 * NN * HH;

    // graph setup (recomputed every call; deterministic up to fp-neutral slot order)
    k_zero<<<196, 256>>>();
    k_count<<<784, 256>>>(edge_dst, node_type);
    k_toff<<<1, 32>>>();
    k_scan<<<1, 1024>>>();
    k_scatter<<<784, 256>>>(node_type, edge_src, edge_dst);

    int tiles = (NN + 31) / 32;
    int nodeblk = (NN + 7) / 8;
    int poscnt = (NN * HH + 255) / 256;

    for (int l = 0; l < LL; l++) {
        k_combine<<<dim3(TT, 2), 256>>>(Wk, Wv, rel_att, rel_msg, rel_pri, l);
        k_pos<<<poscnt, 256>>>(in_hidden, in_x, W_pos, l);
        k_proj<<<dim3(tiles, TT), 128>>>(Wq, l);
        k_edge<<<nodeblk, 256>>>();
        k_out<<<dim3(tiles, TT), 128>>>(Wa, skip, in_cn, in_hidden, out_cn, out_hid, l);
    }
    k_pri<<<nodeblk, 256>>>(w_pri, out_pri);
}

// round 7
// speedup vs baseline: 1.3837x; 1.3837x over previous
#include <cuda_runtime.h>
#include <math.h>

#define NN 50000
#define EE 800000
#define HH 128
#define NHH 8
#define DD 16
#define TT 6
#define LL 2

typedef unsigned long long u64;

// ---------------- scratch (device globals; no allocation allowed) ----------------
__device__ float g_h[NN * HH];       // pos-injected h (per layer)
__device__ float g_kt[NN * HH];      // (h @ WkA[t])  -- rel_att/pri/scale folded in
__device__ float g_q[NN * HH];       // (h @ Wq[t])
__device__ float g_vm[NN * HH];      // (h @ WvM[t])  -- rel_msg folded in
__device__ float g_trans[NN * HH];   // gelu(agg)
__device__ float g_hid[NN * HH];     // hidden state between layers
__device__ float g_cn[NN * HH];      // cn state between layers
__device__ float g_hgt[NN * HH];     // hgt_out (for priority)
__device__ float g_wka[LL * TT * HH * HH];
__device__ float g_wvm[LL * TT * HH * HH];
__device__ int g_tcnt[TT];
__device__ int g_toff[TT + 1];
__device__ int g_tcur[TT];
__device__ int g_tnodes[NN];
__device__ int g_dcnt[NN];
__device__ int g_doff[NN + 1];
__device__ int g_dcur[NN];
__device__ int g_csrc[EE];
__device__ int g_bsum[64];
__device__ int g_bsumoff[64];

// ---------------- helpers ----------------
__device__ __forceinline__ float geluf(float x) {
    float x3 = x * x * x;
    return 0.5f * x * (1.0f + tanhf(0.7978845608028654f * (x + 0.044715f * x3)));
}

__device__ __forceinline__ u64 pack_dup(float w) {
    u64 r;
    asm("mov.b64 %0, {%1, %1};" : "=l"(r) : "f"(w));
    return r;
}
__device__ __forceinline__ void unpack2(u64 v, float& lo, float& hi) {
    asm("mov.b64 {%0, %1}, %2;" : "=f"(lo), "=f"(hi) : "l"(v));
}
__device__ __forceinline__ void fma2(u64& acc, u64 a, u64 b) {
    asm("fma.rn.f32x2 %0, %1, %2, %0;" : "+l"(acc) : "l"(a), "l"(b));
}

// ---------------- setup kernels ----------------
__global__ void k_zero() {
    int i = blockIdx.x * blockDim.x + threadIdx.x;
    int stride = gridDim.x * blockDim.x;
    for (int j = i; j < NN; j += stride) { g_dcnt[j] = 0; g_dcur[j] = 0; }
    if (i < TT) { g_tcnt[i] = 0; g_tcur[i] = 0; }
}

__global__ void k_count(const int* __restrict__ edst, const int* __restrict__ nt) {
    __shared__ int sh[TT];
    int tid = threadIdx.x;
    if (tid < TT) sh[tid] = 0;
    __syncthreads();
    int i = blockIdx.x * blockDim.x + tid;
    int stride = gridDim.x * blockDim.x;
    for (int e = i; e < EE; e += stride) atomicAdd(&g_dcnt[edst[e]], 1);
    for (int n = i; n < NN; n += stride) atomicAdd(&sh[nt[n]], 1);
    __syncthreads();
    if (tid < TT) atomicAdd(&g_tcnt[tid], sh[tid]);
}

// parallel scan, pass A: per-1024-chunk local exclusive scan + chunk totals
__global__ void k_scanA() {
    __shared__ int wsum[32];
    int b = blockIdx.x, tid = threadIdx.x, lane = tid & 31, wid = tid >> 5;
    int i = b * 1024 + tid;
    int v = (i < NN) ? g_dcnt[i] : 0;
    int x = v;
    #pragma unroll
    for (int o = 1; o < 32; o <<= 1) {
        int y = __shfl_up_sync(0xffffffffu, x, o);
        if (lane >= o) x += y;
    }
    if (lane == 31) wsum[wid] = x;
    __syncthreads();
    if (wid == 0) {
        int w = wsum[lane];
        #pragma unroll
        for (int o = 1; o < 32; o <<= 1) {
            int y = __shfl_up_sync(0xffffffffu, w, o);
            if (lane >= o) w += y;
        }
        wsum[lane] = w;
    }
    __syncthreads();
    int incl = x + (wid > 0 ? wsum[wid - 1] : 0);
    if (i < NN) g_doff[i] = incl - v;
    if (tid == 1023) g_bsum[b] = incl;
}

// pass B: serial scan over 49 chunk totals (tiny) + type offsets
__global__ void k_scanB(int nchunks) {
    if (threadIdx.x == 0) {
        int r = 0;
        for (int b = 0; b < nchunks; b++) { g_bsumoff[b] = r; r += g_bsum[b]; }
        g_doff[NN] = r;
    } else if (threadIdx.x == 1) {
        int r = 0;
        for (int t = 0; t < TT; t++) { g_toff[t] = r; r += g_tcnt[t]; }
        g_toff[TT] = r;
    }
}

// pass C: add chunk bases
__global__ void k_scanC() {
    int i = blockIdx.x * blockDim.x + threadIdx.x;
    if (i < NN) g_doff[i] += g_bsumoff[i >> 10];
}

__global__ void k_scatter(const int* __restrict__ nt, const int* __restrict__ esrc,
                          const int* __restrict__ edst) {
    int i = blockIdx.x * blockDim.x + threadIdx.x;
    int stride = gridDim.x * blockDim.x;
    for (int n = i; n < NN; n += stride) {
        int t = nt[n];
        int p = atomicAdd(&g_tcur[t], 1);
        g_tnodes[g_toff[t] + p] = n;
    }
    for (int e = i; e < EE; e += stride) {
        int d = edst[e];
        int p = atomicAdd(&g_dcur[d], 1);
        g_csrc[g_doff[d] + p] = esrc[e];
    }
}

// ---------------- per-layer kernels ----------------
// Fold rel_att (with rel_pri * D^-1/2) into Wk, rel_msg into Wv. All layers at once.
__global__ void k_combine(const float* __restrict__ Wk, const float* __restrict__ Wv,
                          const float* __restrict__ rel_att, const float* __restrict__ rel_msg,
                          const float* __restrict__ rel_pri) {
    int t = blockIdx.x, mat = blockIdx.y, l = blockIdx.z;
    __shared__ float sA[NHH * DD * DD];
    __shared__ float sScl[NHH];
    const float* W = (mat == 0 ? Wk : Wv) + (size_t)(l * TT + t) * HH * HH;
    const float* A = (mat == 0 ? rel_att : rel_msg) + (size_t)l * NHH * DD * DD;
    float* out = (mat == 0 ? g_wka : g_wvm) + (size_t)(l * TT + t) * HH * HH;
    for (int idx = threadIdx.x; idx < NHH * DD * DD; idx += blockDim.x) sA[idx] = A[idx];
    if (threadIdx.x < NHH)
        sScl[threadIdx.x] = (mat == 0) ? rel_pri[l * NHH + threadIdx.x] * 0.25f : 1.0f;
    __syncthreads();
    for (int idx = threadIdx.x; idx < HH * HH; idx += blockDim.x) {
        int i = idx >> 7, c = idx & 127, h = c >> 4, f = c & 15;
        float s = 0.0f;
        #pragma unroll
        for (int d = 0; d < DD; d++)
            s += W[i * HH + h * DD + d] * sA[h * DD * DD + d * DD + f];
        out[idx] = s * sScl[h];
    }
}

// grouped-by-type GEMM with fused positional injection:
// h = hidden + xn@Wpos ; kt/q/vm = h @ {WkA, Wq, WvM}[t].
// 32-node tile, 128 threads, node-pairs packed into f32x2 FFMA2.
__global__ void __launch_bounds__(128) k_proj(const float* __restrict__ Wq,
                                              const float* __restrict__ ext_hidden,
                                              const float* __restrict__ xn,
                                              const float* __restrict__ Wpos, int l) {
    int t = blockIdx.y;
    int beg = g_toff[t], end = g_toff[t + 1];
    int base = beg + (int)blockIdx.x * 32;
    if (base >= end) return;
    int cnt = min(32, end - base);
    __shared__ __align__(8) float hs[HH][34];   // transposed: [feature][node], padded
    __shared__ int nidx[32];
    __shared__ float sxn0[32], sxn1[32];
    int tid = threadIdx.x;
    if (tid < 32) {
        int n = g_tnodes[base + ((tid < cnt) ? tid : 0)];
        nidx[tid] = n;
        sxn0[tid] = xn[2 * n];
        sxn1[tid] = xn[2 * n + 1];
    }
    __syncthreads();
    const float* hin = (l == 0) ? ext_hidden : g_hid;
    float wp0 = Wpos[l * 2 * HH + tid];
    float wp1 = Wpos[l * 2 * HH + HH + tid];
    #pragma unroll 4
    for (int i = 0; i < 32; i++) {
        float hval = 0.0f;
        if (i < cnt) {
            size_t off = (size_t)nidx[i] * HH + tid;
            hval = hin[off] + sxn0[i] * wp0 + sxn1[i] * wp1;
            g_h[off] = hval;
        }
        hs[tid][i] = hval;
    }
    __syncthreads();
    const float* wk = g_wka + (size_t)(l * TT + t) * HH * HH;
    const float* wq = Wq + (size_t)(l * TT + t) * HH * HH;
    const float* wv = g_wvm + (size_t)(l * TT + t) * HH * HH;
    u64 ak[16], aq[16], av[16];
    #pragma unroll
    for (int j = 0; j < 16; j++) { ak[j] = 0ULL; aq[j] = 0ULL; av[j] = 0ULL; }
    #pragma unroll 2
    for (int h = 0; h < HH; h++) {
        u64 wkp = pack_dup(wk[h * HH + tid]);
        u64 wqp = pack_dup(wq[h * HH + tid]);
        u64 wvp = pack_dup(wv[h * HH + tid]);
        const u64* hrow = (const u64*)&hs[h][0];
        #pragma unroll
        for (int j = 0; j < 16; j++) {
            u64 hp = hrow[j];
            fma2(ak[j], hp, wkp);
            fma2(aq[j], hp, wqp);
            fma2(av[j], hp, wvp);
        }
    }
    #pragma unroll
    for (int j = 0; j < 16; j++) {
        float k0, k1, q0, q1, v0, v1;
        unpack2(ak[j], k0, k1);
        unpack2(aq[j], q0, q1);
        unpack2(av[j], v0, v1);
        int i0 = 2 * j, i1 = 2 * j + 1;
        if (i0 < cnt) {
            size_t off = (size_t)nidx[i0] * HH + tid;
            g_kt[off] = k0; g_q[off] = q0; g_vm[off] = v0;
        }
        if (i1 < cnt) {
            size_t off = (size_t)nidx[i1] * HH + tid;
            g_kt[off] = k1; g_q[off] = q1; g_vm[off] = v1;
        }
    }
}

// one warp per destination node: online softmax over incoming edges + message agg + gelu.
// single exp per edge; kt/vm gathers software-pipelined one edge ahead.
__global__ void k_edge() {
    int warp = threadIdx.x >> 5, lane = threadIdx.x & 31;
    int n = blockIdx.x * 8 + warp;
    if (n >= NN) return;
    int beg = g_doff[n], end = g_doff[n + 1];
    float4 q4 = *(const float4*)(g_q + (size_t)n * HH + lane * 4);
    float m = -1e30f, den = 0.0f;
    float ax = 0.f, ay = 0.f, az = 0.f, aw = 0.f;
    for (int b = beg; b < end; b += 32) {
        int nchunk = min(32, end - b);
        int srcs = (b + lane < end) ? g_csrc[b + lane] : 0;
        int src0 = __shfl_sync(0xffffffffu, srcs, 0);
        float4 kt4 = *(const float4*)(g_kt + (size_t)src0 * HH + lane * 4);
        float4 vm4 = *(const float4*)(g_vm + (size_t)src0 * HH + lane * 4);
        for (int j = 0; j < nchunk; j++) {
            float4 ktc = kt4, vmc = vm4;
            if (j + 1 < nchunk) {
                int sn = __shfl_sync(0xffffffffu, srcs, j + 1);
                kt4 = *(const float4*)(g_kt + (size_t)sn * HH + lane * 4);
                vm4 = *(const float4*)(g_vm + (size_t)sn * HH + lane * 4);
            }
            float s = ktc.x * q4.x + ktc.y * q4.y + ktc.z * q4.z + ktc.w * q4.w;
            s += __shfl_xor_sync(0xffffffffu, s, 1);
            s += __shfl_xor_sync(0xffffffffu, s, 2);   // per-head att (head = lane/4)
            float e = __expf(-fabsf(s - m));           // exp(min-max): the only exp
            float sc, p;
            if (s > m) { sc = e; p = 1.0f; m = s; }
            else       { sc = 1.0f; p = e; }
            den = den * sc + p;
            ax = ax * sc + p * vmc.x;
            ay = ay * sc + p * vmc.y;
            az = az * sc + p * vmc.z;
            aw = aw * sc + p * vmc.w;
        }
    }
    float inv = 1.0f / (den + 1e-16f);
    float4 o;
    o.x = geluf(ax * inv);
    o.y = geluf(ay * inv);
    o.z = geluf(az * inv);
    o.w = geluf(aw * inv);
    *(float4*)(g_trans + (size_t)n * HH + lane * 4) = o;
}

// out = trans @ Wa[t] (FFMA2-packed), fused epilogue: skip mix, cn/hidden updates, store hgt
__global__ void __launch_bounds__(128) k_out(const float* __restrict__ Wa,
                                             const float* __restrict__ skip,
                                             const float* __restrict__ ext_cn,
                                             const float* __restrict__ ext_hidden,
                                             float* __restrict__ out_cn,
                                             float* __restrict__ out_hid, int l) {
    int t = blockIdx.y;
    int beg = g_toff[t], end = g_toff[t + 1];
    int base = beg + (int)blockIdx.x * 32;
    if (base >= end) return;
    int cnt = min(32, end - base);
    __shared__ __align__(8) float ts[HH][34];
    __shared__ int nidx[32];
    __shared__ float ssk;
    int tid = threadIdx.x;
    if (tid < 32) nidx[tid] = g_tnodes[base + ((tid < cnt) ? tid : 0)];
    if (tid == 0) ssk = 1.0f / (1.0f + __expf(-skip[l * TT + t]));
    __syncthreads();
    #pragma unroll 4
    for (int i = 0; i < 32; i++)
        ts[tid][i] = (i < cnt) ? g_trans[(size_t)nidx[i] * HH + tid] : 0.0f;
    __syncthreads();
    const float* w = Wa + (size_t)(l * TT + t) * HH * HH;
    u64 acc[16];
    #pragma unroll
    for (int j = 0; j < 16; j++) acc[j] = 0ULL;
    #pragma unroll 2
    for (int h = 0; h < HH; h++) {
        u64 wp = pack_dup(w[h * HH + tid]);
        const u64* trow = (const u64*)&ts[h][0];
        #pragma unroll
        for (int j = 0; j < 16; j++) fma2(acc[j], trow[j], wp);
    }
    const float* cn_in = (l == 0) ? ext_cn : g_cn;
    const float* hid_in = (l == 0) ? ext_hidden : g_hid;
    float* cn_o = (l == LL - 1) ? out_cn : g_cn;
    float* hid_o = (l == LL - 1) ? out_hid : g_hid;
    float sk = ssk;
    #pragma unroll
    for (int j = 0; j < 16; j++) {
        float a0, a1;
        unpack2(acc[j], a0, a1);
        float av[2] = {a0, a1};
        #pragma unroll
        for (int u = 0; u < 2; u++) {
            int i = 2 * j + u;
            if (i < cnt) {
                size_t off = (size_t)nidx[i] * HH + tid;
                float hgt = sk * av[u] + (1.0f - sk) * g_h[off];
                g_hgt[off] = hgt;
                float cnew = hgt + cn_in[off];
                float hnew = hid_in[off] + tanhf(cnew);
                cn_o[off] = cnew;
                hid_o[off] = hnew;
            }
        }
    }
}

// priority = sigmoid(hgt @ w_pri[L-1]); warp per node
__global__ void k_pri(const float* __restrict__ w_pri, float* __restrict__ out) {
    int warp = threadIdx.x >> 5, lane = threadIdx.x & 31;
    int n = blockIdx.x * 8 + warp;
    if (n >= NN) return;
    float4 hv = *(const float4*)(g_hgt + (size_t)n * HH + lane * 4);
    float4 wp = *(const float4*)(w_pri + (LL - 1) * HH + lane * 4);
    float s = hv.x * wp.x + hv.y * wp.y + hv.z * wp.z + hv.w * wp.w;
    #pragma unroll
    for (int o = 16; o > 0; o >>= 1) s += __shfl_xor_sync(0xffffffffu, s, o);
    if (lane == 0) out[n] = 1.0f / (1.0f + __expf(-s));
}

// ---------------- launch ----------------
extern "C" void kernel_launch(void* const* d_in, const int* in_sizes, int n_in,
                              void* d_out, int out_size) {
    const float* in_hidden = (const float*)d_in[0];
    const float* in_cn     = (const float*)d_in[1];
    const float* in_x      = (const float*)d_in[2];
    const int*   node_type = (const int*)d_in[3];
    const int*   edge_src  = (const int*)d_in[4];
    const int*   edge_dst  = (const int*)d_in[5];
    const float* W_pos     = (const float*)d_in[6];
    const float* Wk        = (const float*)d_in[7];
    const float* Wq        = (const float*)d_in[8];
    const float* Wv        = (const float*)d_in[9];
    const float* Wa        = (const float*)d_in[10];
    const float* rel_att   = (const float*)d_in[11];
    const float* rel_msg   = (const float*)d_in[12];
    const float* rel_pri   = (const float*)d_in[13];
    const float* skip      = (const float*)d_in[14];
    const float* w_pri     = (const float*)d_in[15];

    float* out = (float*)d_out;
    float* out_hid = out;
    float* out_cn = out + (size_t)NN * HH;
    float* out_pri = out + (size_t)2 * NN * HH;

    int nchunks = (NN + 1023) / 1024;  // 49

    // graph setup (recomputed every call; deterministic up to fp-neutral slot order)
    k_zero<<<196, 256>>>();
    k_count<<<784, 256>>>(edge_dst, node_type);
    k_scanA<<<nchunks, 1024>>>();
    k_scanB<<<1, 32>>>(nchunks);
    k_scanC<<<196, 256>>>();
    k_scatter<<<784, 256>>>(node_type, edge_src, edge_dst);
    k_combine<<<dim3(TT, 2, LL), 256>>>(Wk, Wv, rel_att, rel_msg, rel_pri);

    int tiles = (NN + 31) / 32;
    int nodeblk = (NN + 7) / 8;

    for (int l = 0; l < LL; l++) {
        k_proj<<<dim3(tiles, TT), 128>>>(Wq, in_hidden, in_x, W_pos, l);
        k_edge<<<nodeblk, 256>>>();
        k_out<<<dim3(tiles, TT), 128>>>(Wa, skip, in_cn, in_hidden, out_cn, out_hid, l);
    }
    k_pri<<<nodeblk, 256>>>(w_pri, out_pri);
}

// round 8
// speedup vs baseline: 1.4306x; 1.0339x over previous
#include <cuda_runtime.h>
#include <math.h>

#define NN 50000
#define EE 800000
#define HH 128
#define NHH 8
#define DD 16
#define TT 6
#define LL 2

typedef unsigned long long u64;

// ---------------- scratch (device globals; no allocation allowed) ----------------
__device__ float g_h[NN * HH];       // pos-injected h (per layer)
__device__ float g_kt[NN * HH];      // (h @ WkA[t])  -- rel_att/pri/scale folded in
__device__ float g_q[NN * HH];       // (h @ Wq[t])
__device__ float g_vm[NN * HH];      // (h @ WvM[t])  -- rel_msg folded in
__device__ float g_trans[NN * HH];   // gelu(agg)
__device__ float g_hid[NN * HH];     // hidden state between layers
__device__ float g_cn[NN * HH];      // cn state between layers
__device__ float g_hgt[NN * HH];     // hgt_out (for priority)
__device__ float g_wka[LL * TT * HH * HH];
__device__ float g_wvm[LL * TT * HH * HH];
__device__ int g_tcnt[TT];
__device__ int g_toff[TT + 1];
__device__ int g_tcur[TT];
__device__ int g_tnodes[NN];
__device__ int g_dcnt[NN];
__device__ int g_doff[NN + 1];
__device__ int g_dcur[NN];
__device__ int g_csrc[EE];
__device__ int g_bsum[64];
__device__ int g_bsumoff[64];

// ---------------- helpers ----------------
__device__ __forceinline__ float geluf(float x) {
    float x3 = x * x * x;
    return 0.5f * x * (1.0f + tanhf(0.7978845608028654f * (x + 0.044715f * x3)));
}

__device__ __forceinline__ u64 pack_dup(float w) {
    u64 r;
    asm("mov.b64 %0, {%1, %1};" : "=l"(r) : "f"(w));
    return r;
}
__device__ __forceinline__ void unpack2(u64 v, float& lo, float& hi) {
    asm("mov.b64 {%0, %1}, %2;" : "=f"(lo), "=f"(hi) : "l"(v));
}
__device__ __forceinline__ void fma2(u64& acc, u64 a, u64 b) {
    asm("fma.rn.f32x2 %0, %1, %2, %0;" : "+l"(acc) : "l"(a), "l"(b));
}

// ---------------- setup kernels ----------------
__global__ void k_zero() {
    int i = blockIdx.x * blockDim.x + threadIdx.x;
    int stride = gridDim.x * blockDim.x;
    for (int j = i; j < NN; j += stride) { g_dcnt[j] = 0; g_dcur[j] = 0; }
    if (i < TT) { g_tcnt[i] = 0; g_tcur[i] = 0; }
}

__global__ void k_count(const int* __restrict__ edst, const int* __restrict__ nt) {
    __shared__ int sh[TT];
    int tid = threadIdx.x;
    if (tid < TT) sh[tid] = 0;
    __syncthreads();
    int i = blockIdx.x * blockDim.x + tid;
    int stride = gridDim.x * blockDim.x;
    for (int e = i; e < EE; e += stride) atomicAdd(&g_dcnt[edst[e]], 1);
    for (int n = i; n < NN; n += stride) atomicAdd(&sh[nt[n]], 1);
    __syncthreads();
    if (tid < TT) atomicAdd(&g_tcnt[tid], sh[tid]);
}

// parallel scan, pass A: per-1024-chunk local exclusive scan + chunk totals
__global__ void k_scanA() {
    __shared__ int wsum[32];
    int b = blockIdx.x, tid = threadIdx.x, lane = tid & 31, wid = tid >> 5;
    int i = b * 1024 + tid;
    int v = (i < NN) ? g_dcnt[i] : 0;
    int x = v;
    #pragma unroll
    for (int o = 1; o < 32; o <<= 1) {
        int y = __shfl_up_sync(0xffffffffu, x, o);
        if (lane >= o) x += y;
    }
    if (lane == 31) wsum[wid] = x;
    __syncthreads();
    if (wid == 0) {
        int w = wsum[lane];
        #pragma unroll
        for (int o = 1; o < 32; o <<= 1) {
            int y = __shfl_up_sync(0xffffffffu, w, o);
            if (lane >= o) w += y;
        }
        wsum[lane] = w;
    }
    __syncthreads();
    int incl = x + (wid > 0 ? wsum[wid - 1] : 0);
    if (i < NN) g_doff[i] = incl - v;
    if (tid == 1023) g_bsum[b] = incl;
}

// pass B: serial scan over 49 chunk totals (tiny) + type offsets
__global__ void k_scanB(int nchunks) {
    if (threadIdx.x == 0) {
        int r = 0;
        for (int b = 0; b < nchunks; b++) { g_bsumoff[b] = r; r += g_bsum[b]; }
        g_doff[NN] = r;
    } else if (threadIdx.x == 1) {
        int r = 0;
        for (int t = 0; t < TT; t++) { g_toff[t] = r; r += g_tcnt[t]; }
        g_toff[TT] = r;
    }
}

// pass C: add chunk bases
__global__ void k_scanC() {
    int i = blockIdx.x * blockDim.x + threadIdx.x;
    if (i < NN) g_doff[i] += g_bsumoff[i >> 10];
}

__global__ void k_scatter(const int* __restrict__ nt, const int* __restrict__ esrc,
                          const int* __restrict__ edst) {
    int i = blockIdx.x * blockDim.x + threadIdx.x;
    int stride = gridDim.x * blockDim.x;
    for (int n = i; n < NN; n += stride) {
        int t = nt[n];
        int p = atomicAdd(&g_tcur[t], 1);
        g_tnodes[g_toff[t] + p] = n;
    }
    for (int e = i; e < EE; e += stride) {
        int d = edst[e];
        int p = atomicAdd(&g_dcur[d], 1);
        g_csrc[g_doff[d] + p] = esrc[e];
    }
}

// ---------------- per-layer kernels ----------------
// Fold rel_att (with rel_pri * D^-1/2) into Wk, rel_msg into Wv. All layers at once.
__global__ void k_combine(const float* __restrict__ Wk, const float* __restrict__ Wv,
                          const float* __restrict__ rel_att, const float* __restrict__ rel_msg,
                          const float* __restrict__ rel_pri) {
    int t = blockIdx.x, mat = blockIdx.y, l = blockIdx.z;
    __shared__ float sA[NHH * DD * DD];
    __shared__ float sScl[NHH];
    const float* W = (mat == 0 ? Wk : Wv) + (size_t)(l * TT + t) * HH * HH;
    const float* A = (mat == 0 ? rel_att : rel_msg) + (size_t)l * NHH * DD * DD;
    float* out = (mat == 0 ? g_wka : g_wvm) + (size_t)(l * TT + t) * HH * HH;
    for (int idx = threadIdx.x; idx < NHH * DD * DD; idx += blockDim.x) sA[idx] = A[idx];
    if (threadIdx.x < NHH)
        sScl[threadIdx.x] = (mat == 0) ? rel_pri[l * NHH + threadIdx.x] * 0.25f : 1.0f;
    __syncthreads();
    for (int idx = threadIdx.x; idx < HH * HH; idx += blockDim.x) {
        int i = idx >> 7, c = idx & 127, h = c >> 4, f = c & 15;
        float s = 0.0f;
        #pragma unroll
        for (int d = 0; d < DD; d++)
            s += W[i * HH + h * DD + d] * sA[h * DD * DD + d * DD + f];
        out[idx] = s * sScl[h];
    }
}

// grouped-by-type GEMM with fused positional injection:
// h = hidden + xn@Wpos ; kt/q/vm = h @ {WkA, Wq, WvM}[t].
// 32-node tile, 128 threads, node-pairs packed into f32x2 FFMA2.
__global__ void __launch_bounds__(128) k_proj(const float* __restrict__ Wq,
                                              const float* __restrict__ ext_hidden,
                                              const float* __restrict__ xn,
                                              const float* __restrict__ Wpos, int l) {
    int t = blockIdx.y;
    int beg = g_toff[t], end = g_toff[t + 1];
    int base = beg + (int)blockIdx.x * 32;
    if (base >= end) return;
    int cnt = min(32, end - base);
    __shared__ __align__(8) float hs[HH][34];   // transposed: [feature][node], padded
    __shared__ int nidx[32];
    __shared__ float sxn0[32], sxn1[32];
    int tid = threadIdx.x;
    if (tid < 32) {
        int n = g_tnodes[base + ((tid < cnt) ? tid : 0)];
        nidx[tid] = n;
        sxn0[tid] = xn[2 * n];
        sxn1[tid] = xn[2 * n + 1];
    }
    __syncthreads();
    const float* hin = (l == 0) ? ext_hidden : g_hid;
    float wp0 = Wpos[l * 2 * HH + tid];
    float wp1 = Wpos[l * 2 * HH + HH + tid];
    #pragma unroll 4
    for (int i = 0; i < 32; i++) {
        float hval = 0.0f;
        if (i < cnt) {
            size_t off = (size_t)nidx[i] * HH + tid;
            hval = hin[off] + sxn0[i] * wp0 + sxn1[i] * wp1;
            g_h[off] = hval;
        }
        hs[tid][i] = hval;
    }
    __syncthreads();
    const float* wk = g_wka + (size_t)(l * TT + t) * HH * HH;
    const float* wq = Wq + (size_t)(l * TT + t) * HH * HH;
    const float* wv = g_wvm + (size_t)(l * TT + t) * HH * HH;
    u64 ak[16], aq[16], av[16];
    #pragma unroll
    for (int j = 0; j < 16; j++) { ak[j] = 0ULL; aq[j] = 0ULL; av[j] = 0ULL; }
    #pragma unroll 2
    for (int h = 0; h < HH; h++) {
        u64 wkp = pack_dup(wk[h * HH + tid]);
        u64 wqp = pack_dup(wq[h * HH + tid]);
        u64 wvp = pack_dup(wv[h * HH + tid]);
        const u64* hrow = (const u64*)&hs[h][0];
        #pragma unroll
        for (int j = 0; j < 16; j++) {
            u64 hp = hrow[j];
            fma2(ak[j], hp, wkp);
            fma2(aq[j], hp, wqp);
            fma2(av[j], hp, wvp);
        }
    }
    #pragma unroll
    for (int j = 0; j < 16; j++) {
        float k0, k1, q0, q1, v0, v1;
        unpack2(ak[j], k0, k1);
        unpack2(aq[j], q0, q1);
        unpack2(av[j], v0, v1);
        int i0 = 2 * j, i1 = 2 * j + 1;
        if (i0 < cnt) {
            size_t off = (size_t)nidx[i0] * HH + tid;
            g_kt[off] = k0; g_q[off] = q0; g_vm[off] = v0;
        }
        if (i1 < cnt) {
            size_t off = (size_t)nidx[i1] * HH + tid;
            g_kt[off] = k1; g_q[off] = q1; g_vm[off] = v1;
        }
    }
}

// one warp per destination node. Max-free softmax: anchor C = first edge's score
// (any constant gives identical alpha mathematically; first-edge anchor keeps
// exponents small without a serial running-max chain). Edges are then fully
// independent iterations -> unroll x2 with dual accumulator sets for MLP.
__global__ void k_edge() {
    int warp = threadIdx.x >> 5, lane = threadIdx.x & 31;
    int n = blockIdx.x * 8 + warp;
    if (n >= NN) return;
    int beg = g_doff[n], end = g_doff[n + 1];
    float* outp = g_trans + (size_t)n * HH + lane * 4;
    if (beg == end) {   // no incoming edges: agg=0 -> gelu(0)=0
        *(float4*)outp = make_float4(0.f, 0.f, 0.f, 0.f);
        return;
    }
    float4 q4 = *(const float4*)(g_q + (size_t)n * HH + lane * 4);

    // first edge: anchor
    int src0 = g_csrc[beg];
    float4 k0 = *(const float4*)(g_kt + (size_t)src0 * HH + lane * 4);
    float4 v0 = *(const float4*)(g_vm + (size_t)src0 * HH + lane * 4);
    float C = k0.x * q4.x + k0.y * q4.y + k0.z * q4.z + k0.w * q4.w;
    C += __shfl_xor_sync(0xffffffffu, C, 1);
    C += __shfl_xor_sync(0xffffffffu, C, 2);   // per-head score (head = lane/4)

    float den0 = 1.0f, den1 = 0.0f;            // first edge: p = exp(0) = 1
    float ax0 = v0.x, ay0 = v0.y, az0 = v0.z, aw0 = v0.w;
    float ax1 = 0.f, ay1 = 0.f, az1 = 0.f, aw1 = 0.f;

    for (int b = beg + 1; b < end; b += 32) {
        int nchunk = min(32, end - b);
        int srcs = (b + lane < end) ? g_csrc[b + lane] : 0;
        int j = 0;
        for (; j + 2 <= nchunk; j += 2) {
            int sA = __shfl_sync(0xffffffffu, srcs, j);
            int sB = __shfl_sync(0xffffffffu, srcs, j + 1);
            float4 kA = *(const float4*)(g_kt + (size_t)sA * HH + lane * 4);
            float4 kB = *(const float4*)(g_kt + (size_t)sB * HH + lane * 4);
            float4 vA = *(const float4*)(g_vm + (size_t)sA * HH + lane * 4);
            float4 vB = *(const float4*)(g_vm + (size_t)sB * HH + lane * 4);
            float sa = kA.x * q4.x + kA.y * q4.y + kA.z * q4.z + kA.w * q4.w;
            float sb = kB.x * q4.x + kB.y * q4.y + kB.z * q4.z + kB.w * q4.w;
            sa += __shfl_xor_sync(0xffffffffu, sa, 1);
            sb += __shfl_xor_sync(0xffffffffu, sb, 1);
            sa += __shfl_xor_sync(0xffffffffu, sa, 2);
            sb += __shfl_xor_sync(0xffffffffu, sb, 2);
            float pa = __expf(sa - C);
            float pb = __expf(sb - C);
            den0 += pa;             den1 += pb;
            ax0 += pa * vA.x;       ax1 += pb * vB.x;
            ay0 += pa * vA.y;       ay1 += pb * vB.y;
            az0 += pa * vA.z;       az1 += pb * vB.z;
            aw0 += pa * vA.w;       aw1 += pb * vB.w;
        }
        if (j < nchunk) {
            int sA = __shfl_sync(0xffffffffu, srcs, j);
            float4 kA = *(const float4*)(g_kt + (size_t)sA * HH + lane * 4);
            float4 vA = *(const float4*)(g_vm + (size_t)sA * HH + lane * 4);
            float sa = kA.x * q4.x + kA.y * q4.y + kA.z * q4.z + kA.w * q4.w;
            sa += __shfl_xor_sync(0xffffffffu, sa, 1);
            sa += __shfl_xor_sync(0xffffffffu, sa, 2);
            float pa = __expf(sa - C);
            den0 += pa;
            ax0 += pa * vA.x; ay0 += pa * vA.y;
            az0 += pa * vA.z; aw0 += pa * vA.w;
        }
    }
    float inv = 1.0f / (den0 + den1 + 1e-16f);
    float4 o;
    o.x = geluf((ax0 + ax1) * inv);
    o.y = geluf((ay0 + ay1) * inv);
    o.z = geluf((az0 + az1) * inv);
    o.w = geluf((aw0 + aw1) * inv);
    *(float4*)outp = o;
}

// out = trans @ Wa[t] (FFMA2-packed), fused epilogue: skip mix, cn/hidden updates, store hgt
__global__ void __launch_bounds__(128) k_out(const float* __restrict__ Wa,
                                             const float* __restrict__ skip,
                                             const float* __restrict__ ext_cn,
                                             const float* __restrict__ ext_hidden,
                                             float* __restrict__ out_cn,
                                             float* __restrict__ out_hid, int l) {
    int t = blockIdx.y;
    int beg = g_toff[t], end = g_toff[t + 1];
    int base = beg + (int)blockIdx.x * 32;
    if (base >= end) return;
    int cnt = min(32, end - base);
    __shared__ __align__(8) float ts[HH][34];
    __shared__ int nidx[32];
    __shared__ float ssk;
    int tid = threadIdx.x;
    if (tid < 32) nidx[tid] = g_tnodes[base + ((tid < cnt) ? tid : 0)];
    if (tid == 0) ssk = 1.0f / (1.0f + __expf(-skip[l * TT + t]));
    __syncthreads();
    #pragma unroll 4
    for (int i = 0; i < 32; i++)
        ts[tid][i] = (i < cnt) ? g_trans[(size_t)nidx[i] * HH + tid] : 0.0f;
    __syncthreads();
    const float* w = Wa + (size_t)(l * TT + t) * HH * HH;
    u64 acc[16];
    #pragma unroll
    for (int j = 0; j < 16; j++) acc[j] = 0ULL;
    #pragma unroll 2
    for (int h = 0; h < HH; h++) {
        u64 wp = pack_dup(w[h * HH + tid]);
        const u64* trow = (const u64*)&ts[h][0];
        #pragma unroll
        for (int j = 0; j < 16; j++) fma2(acc[j], trow[j], wp);
    }
    const float* cn_in = (l == 0) ? ext_cn : g_cn;
    const float* hid_in = (l == 0) ? ext_hidden : g_hid;
    float* cn_o = (l == LL - 1) ? out_cn : g_cn;
    float* hid_o = (l == LL - 1) ? out_hid : g_hid;
    float sk = ssk;
    #pragma unroll
    for (int j = 0; j < 16; j++) {
        float a0, a1;
        unpack2(acc[j], a0, a1);
        float av[2] = {a0, a1};
        #pragma unroll
        for (int u = 0; u < 2; u++) {
            int i = 2 * j + u;
            if (i < cnt) {
                size_t off = (size_t)nidx[i] * HH + tid;
                float hgt = sk * av[u] + (1.0f - sk) * g_h[off];
                g_hgt[off] = hgt;
                float cnew = hgt + cn_in[off];
                float hnew = hid_in[off] + tanhf(cnew);
                cn_o[off] = cnew;
                hid_o[off] = hnew;
            }
        }
    }
}

// priority = sigmoid(hgt @ w_pri[L-1]); warp per node
__global__ void k_pri(const float* __restrict__ w_pri, float* __restrict__ out) {
    int warp = threadIdx.x >> 5, lane = threadIdx.x & 31;
    int n = blockIdx.x * 8 + warp;
    if (n >= NN) return;
    float4 hv = *(const float4*)(g_hgt + (size_t)n * HH + lane * 4);
    float4 wp = *(const float4*)(w_pri + (LL - 1) * HH + lane * 4);
    float s = hv.x * wp.x + hv.y * wp.y + hv.z * wp.z + hv.w * wp.w;
    #pragma unroll
    for (int o = 16; o > 0; o >>= 1) s += __shfl_xor_sync(0xffffffffu, s, o);
    if (lane == 0) out[n] = 1.0f / (1.0f + __expf(-s));
}

// ---------------- launch ----------------
extern "C" void kernel_launch(void* const* d_in, const int* in_sizes, int n_in,
                              void* d_out, int out_size) {
    const float* in_hidden = (const float*)d_in[0];
    const float* in_cn     = (const float*)d_in[1];
    const float* in_x      = (const float*)d_in[2];
    const int*   node_type = (const int*)d_in[3];
    const int*   edge_src  = (const int*)d_in[4];
    const int*   edge_dst  = (const int*)d_in[5];
    const float* W_pos     = (const float*)d_in[6];
    const float* Wk        = (const float*)d_in[7];
    const float* Wq        = (const float*)d_in[8];
    const float* Wv        = (const float*)d_in[9];
    const float* Wa        = (const float*)d_in[10];
    const float* rel_att   = (const float*)d_in[11];
    const float* rel_msg   = (const float*)d_in[12];
    const float* rel_pri   = (const float*)d_in[13];
    const float* skip      = (const float*)d_in[14];
    const float* w_pri     = (const float*)d_in[15];

    float* out = (float*)d_out;
    float* out_hid = out;
    float* out_cn = out + (size_t)NN * HH;
    float* out_pri = out + (size_t)2 * NN * HH;

    int nchunks = (NN + 1023) / 1024;  // 49

    // graph setup (recomputed every call; deterministic up to fp-neutral slot order)
    k_zero<<<196, 256>>>();
    k_count<<<784, 256>>>(edge_dst, node_type);
    k_scanA<<<nchunks, 1024>>>();
    k_scanB<<<1, 32>>>(nchunks);
    k_scanC<<<196, 256>>>();
    k_scatter<<<784, 256>>>(node_type, edge_src, edge_dst);
    k_combine<<<dim3(TT, 2, LL), 256>>>(Wk, Wv, rel_att, rel_msg, rel_pri);

    int tiles = (NN + 31) / 32;
    int nodeblk = (NN + 7) / 8;

    for (int l = 0; l < LL; l++) {
        k_proj<<<dim3(tiles, TT), 128>>>(Wq, in_hidden, in_x, W_pos, l);
        k_edge<<<nodeblk, 256>>>();
        k_out<<<dim3(tiles, TT), 128>>>(Wa, skip, in_cn, in_hidden, out_cn, out_hid, l);
    }
    k_pri<<<nodeblk, 256>>>(w_pri, out_pri);
}